// round 8
// baseline (speedup 1.0000x reference)
#include <cuda_runtime.h>
#include <math.h>

// Problem constants: generated [2, 3, 96, 96]
#define B       2
#define NPIX    9216            // 96*96
#define TOTQ    (B * NPIX)      // 18432 queries
#define K       8               // NUM_CLUSTERS
#define NTHR    256
#define QPT     4               // queries per thread (mask kernel)
#define QPB     (NTHR * QPT)    // 1024
#define NQG     (NPIX / QPB)    // 9 query groups per batch

#define SAMPN   576             // threshold sample = chunk 0
#define NCHUNKB 32
#define CHUNK   (NPIX / NCHUNKB)   // 288 candidates per mask-scan chunk
#define WPC     (CHUNK / 32)       // 9 mask words per chunk
#define NWORDS  (NPIX / 32)        // 288 mask words per query

#define CBLK    (TOTQ / NTHR)      // 72 blocks for thresh/select

typedef unsigned long long u64;

// Device scratch (allocation-free rule: __device__ globals)
__device__ float4     g_cand[B * NPIX];        // {-2x,-2y,-2z,|c|^2}
__device__ ulonglong2 g_pairA[B * NPIX / 2];   // {x0,x1},{y0,y1} per cand pair
__device__ ulonglong2 g_pairB[B * NPIX / 2];   // {z0,z1},{w0,w1}
__device__ float      g_thr[TOTQ];             // per-query threshold (score)
__device__ unsigned   g_mask[NWORDS][TOTQ];    // survivor bitmask, word-major
__device__ float      g_bsum[CBLK];
__device__ unsigned   g_ticket;                // zero-init; reset after use

// ---- packed helpers -------------------------------------------------------
__device__ __forceinline__ u64 fma2(u64 a, u64 b, u64 c) {
    u64 d;
    asm("fma.rn.f32x2 %0, %1, %2, %3;" : "=l"(d) : "l"(a), "l"(b), "l"(c));
    return d;
}
__device__ __forceinline__ u64 pack2(float lo, float hi) {
    u64 d;
    asm("mov.b64 %0, {%1, %2};" : "=l"(d) : "f"(lo), "f"(hi));
    return d;
}
__device__ __forceinline__ float2 unpack2(u64 v) {
    float2 r;
    asm("mov.b64 {%0, %1}, %2;" : "=f"(r.x), "=f"(r.y) : "l"(v));
    return r;
}

// Scalar compare-exchange insert into sorted-ascending t[0..K-1].
// Constant indexing only -- must stay in registers.
__device__ __forceinline__ void insert8s(float (&t)[K], float u) {
    #pragma unroll
    for (int k = 0; k < K; k++) {
        float lo = fminf(t[k], u);
        u = fmaxf(t[k], u);
        t[k] = lo;
    }
}

// ---------------------------------------------------------------------------
// Kernel 1: pack candidates (plain float4 + pair-interleaved for f32x2)
// ---------------------------------------------------------------------------
__global__ void prep_kernel(const float* __restrict__ in) {
    int idx = blockIdx.x * blockDim.x + threadIdx.x;   // [0, TOTQ)
    if (idx >= TOTQ) return;
    int b = idx / NPIX;
    int i = idx - b * NPIX;
    const float* base = in + (size_t)b * 3 * NPIX;
    float x = base[i];
    float y = base[NPIX + i];
    float z = base[2 * NPIX + i];
    float s = x * x + y * y + z * z;
    float mx = -2.0f * x, my = -2.0f * y, mz = -2.0f * z;
    g_cand[idx] = make_float4(mx, my, mz, s);
    int p = idx >> 1, h = idx & 1;        // NPIX even -> pairs stay in-batch
    float* pa = (float*)&g_pairA[p];
    float* pb = (float*)&g_pairB[p];
    pa[h]     = mx;  pa[2 + h] = my;
    pb[h]     = mz;  pb[2 + h] = s;
}

// ---------------------------------------------------------------------------
// Kernel 2: per-query threshold = 8th-smallest score over chunk 0 (+1 ulp).
// 1 query per thread, conditional CE inserts (arrays constant-indexed).
// ---------------------------------------------------------------------------
__global__ void __launch_bounds__(NTHR)
thresh_kernel(const float* __restrict__ in) {
    __shared__ float4 sh[SAMPN];   // 9216 B

    int tid = threadIdx.x;
    int q = blockIdx.x * NTHR + tid;     // [0, TOTQ)
    int b = q / NPIX;
    int qi = q - b * NPIX;

    for (int i = tid; i < SAMPN; i += NTHR) sh[i] = g_cand[b * NPIX + i];

    const float* base = in + (size_t)b * 3 * NPIX;
    float ax = base[qi], ay = base[NPIX + qi], az = base[2 * NPIX + qi];

    float t[K];
    #pragma unroll
    for (int k = 0; k < K; k++) t[k] = 3.0e30f;

    __syncthreads();

    // bootstrap: first 16 unconditional
    for (int j = 0; j < 16; j++) {
        float4 cv = sh[j];
        insert8s(t, fmaf(ax, cv.x, fmaf(ay, cv.y, fmaf(az, cv.z, cv.w))));
    }
    #pragma unroll 4
    for (int j = 16; j < SAMPN; j++) {
        float4 cv = sh[j];
        float d = fmaf(ax, cv.x, fmaf(ay, cv.y, fmaf(az, cv.z, cv.w)));
        if (d < t[K - 1]) insert8s(t, d);
    }
    // strict-< gate downstream must admit d == T -> open the bound one ulp
    g_thr[q] = nextafterf(t[K - 1], 3.4e38f);
}

// ---------------------------------------------------------------------------
// Kernel 3 (HOT): branch-free mask scan. For every (query, candidate) pair
// compute score via packed FFMA2 and record (score < T_q) as one bit.
// No selection state, no branches, no shared stores in the loop.
// ---------------------------------------------------------------------------
__global__ void __launch_bounds__(NTHR)
mask_kernel(const float* __restrict__ in) {
    __shared__ ulonglong2 shA[CHUNK / 2];   // 144 * 16B
    __shared__ ulonglong2 shB[CHUNK / 2];   // 144 * 16B

    int bid = blockIdx.x;                 // [0, B*NQG*NCHUNKB) = [0, 576)
    int c   = bid & (NCHUNKB - 1);
    int qg  = (bid >> 5) % NQG;
    int b   = bid / (NQG * NCHUNKB);

    int tid = threadIdx.x;
    int poff = b * (NPIX / 2) + c * (CHUNK / 2);
    for (int i = tid; i < CHUNK / 2; i += NTHR) {
        shA[i] = g_pairA[poff + i];
        shB[i] = g_pairB[poff + i];
    }

    int q0 = qg * QPB + tid;
    int gq = b * NPIX + q0;
    const float* base = in + (size_t)b * 3 * NPIX;
    float a0x = base[q0],            a0y = base[NPIX + q0],            a0z = base[2*NPIX + q0];
    float a1x = base[q0 + NTHR],     a1y = base[NPIX + q0 + NTHR],     a1z = base[2*NPIX + q0 + NTHR];
    float a2x = base[q0 + 2*NTHR],   a2y = base[NPIX + q0 + 2*NTHR],   a2z = base[2*NPIX + q0 + 2*NTHR];
    float a3x = base[q0 + 3*NTHR],   a3y = base[NPIX + q0 + 3*NTHR],   a3z = base[2*NPIX + q0 + 3*NTHR];
    u64 QX0 = pack2(a0x, a0x), QY0 = pack2(a0y, a0y), QZ0 = pack2(a0z, a0z);
    u64 QX1 = pack2(a1x, a1x), QY1 = pack2(a1y, a1y), QZ1 = pack2(a1z, a1z);
    u64 QX2 = pack2(a2x, a2x), QY2 = pack2(a2y, a2y), QZ2 = pack2(a2z, a2z);
    u64 QX3 = pack2(a3x, a3x), QY3 = pack2(a3y, a3y), QZ3 = pack2(a3z, a3z);

    float m0 = g_thr[gq];
    float m1 = g_thr[gq + NTHR];
    float m2 = g_thr[gq + 2 * NTHR];
    float m3 = g_thr[gq + 3 * NTHR];

    __syncthreads();

    for (int s16 = 0; s16 < CHUNK / 2; s16 += 16) {   // 16 pairs = 32 cands = 1 word
        unsigned M0 = 0, M1 = 0, M2 = 0, M3 = 0;
        #pragma unroll
        for (int u = 0; u < 16; u++) {
            ulonglong2 pA = shA[s16 + u];
            ulonglong2 pB = shB[s16 + u];
            u64 d0 = fma2(QX0, pA.x, fma2(QY0, pA.y, fma2(QZ0, pB.x, pB.y)));
            u64 d1 = fma2(QX1, pA.x, fma2(QY1, pA.y, fma2(QZ1, pB.x, pB.y)));
            u64 d2 = fma2(QX2, pA.x, fma2(QY2, pA.y, fma2(QZ2, pB.x, pB.y)));
            u64 d3 = fma2(QX3, pA.x, fma2(QY3, pA.y, fma2(QZ3, pB.x, pB.y)));
            float2 e0 = unpack2(d0);
            float2 e1 = unpack2(d1);
            float2 e2 = unpack2(d2);
            float2 e3 = unpack2(d3);
            if (e0.x < m0) M0 |= (1u << (2 * u));
            if (e0.y < m0) M0 |= (1u << (2 * u + 1));
            if (e1.x < m1) M1 |= (1u << (2 * u));
            if (e1.y < m1) M1 |= (1u << (2 * u + 1));
            if (e2.x < m2) M2 |= (1u << (2 * u));
            if (e2.y < m2) M2 |= (1u << (2 * u + 1));
            if (e3.x < m3) M3 |= (1u << (2 * u));
            if (e3.y < m3) M3 |= (1u << (2 * u + 1));
        }
        int w = c * WPC + (s16 >> 4);
        g_mask[w][gq]            = M0;     // coalesced across threads
        g_mask[w][gq + NTHR]     = M1;
        g_mask[w][gq + 2 * NTHR] = M2;
        g_mask[w][gq + 3 * NTHR] = M3;
    }
}

// ---------------------------------------------------------------------------
// Kernel 4: select exact top-8 from mask survivors, sum 7 sqrt distances
// (smallest = self -> 0), fused block + final reduction via ticket.
// ---------------------------------------------------------------------------
__global__ void __launch_bounds__(NTHR)
select_kernel(const float* __restrict__ in, float* __restrict__ out) {
    __shared__ float red[NTHR];
    __shared__ int islast;

    int tid = threadIdx.x;
    int q = blockIdx.x * NTHR + tid;     // [0, TOTQ)
    int b = q / NPIX;
    int qi = q - b * NPIX;
    const float* base = in + (size_t)b * 3 * NPIX;
    float ax = base[qi], ay = base[NPIX + qi], az = base[2 * NPIX + qi];
    float q2 = fmaf(ax, ax, fmaf(ay, ay, az * az));

    float t[K];
    #pragma unroll
    for (int k = 0; k < K; k++) t[k] = 3.0e30f;

    const float4* cb = g_cand + b * NPIX;
    #pragma unroll 4
    for (int w = 0; w < NWORDS; w++) {
        unsigned word = g_mask[w][q];
        while (word) {
            int bit = __ffs(word) - 1;
            word &= word - 1;
            float4 cv = cb[w * 32 + bit];
            float d = fmaf(ax, cv.x, fmaf(ay, cv.y, fmaf(az, cv.z, cv.w)));
            if (d < t[K - 1]) insert8s(t, d);
        }
    }

    // t[0] is the self-distance (reference value: exactly 0) -> contribute 0.
    float s = 0.0f;
    #pragma unroll
    for (int k = 1; k < K; k++) s += sqrtf(fmaxf(t[k] + q2, 0.0f));

    red[tid] = s;
    __syncthreads();
    #pragma unroll
    for (int w = NTHR / 2; w > 0; w >>= 1) {
        if (tid < w) red[tid] += red[tid + w];
        __syncthreads();
    }
    if (tid == 0) {
        g_bsum[blockIdx.x] = red[0];
        __threadfence();
        unsigned r = atomicAdd(&g_ticket, 1u);
        islast = (r == (unsigned)(gridDim.x - 1));
    }
    __syncthreads();

    if (islast) {
        float v = (tid < CBLK) ? __ldcg(&g_bsum[tid]) : 0.0f;
        red[tid] = v;
        __syncthreads();
        #pragma unroll
        for (int w = NTHR / 2; w > 0; w >>= 1) {
            if (tid < w) red[tid] += red[tid + w];
            __syncthreads();
        }
        if (tid == 0) {
            out[0] = -red[0] / (float)(TOTQ * K);
            g_ticket = 0;    // reset for next graph replay
        }
    }
}

extern "C" void kernel_launch(void* const* d_in, const int* in_sizes, int n_in,
                              void* d_out, int out_size) {
    const float* in = (const float*)d_in[0];
    float* out = (float*)d_out;

    prep_kernel<<<(TOTQ + NTHR - 1) / NTHR, NTHR>>>(in);
    thresh_kernel<<<CBLK, NTHR>>>(in);
    mask_kernel<<<B * NQG * NCHUNKB, NTHR>>>(in);
    select_kernel<<<CBLK, NTHR>>>(in, out);
}

// round 10
// speedup vs baseline: 2.2526x; 2.2526x over previous
#include <cuda_runtime.h>
#include <math.h>

// Problem constants: generated [2, 3, 96, 96]
#define B       2
#define NPIX    9216            // 96*96
#define TOTQ    (B * NPIX)      // 18432 queries
#define K       8               // NUM_CLUSTERS
#define NTHR    256
#define QPT     4               // queries per thread (mask kernel)
#define QPB     (NTHR * QPT)    // 1024
#define NQG     (NPIX / QPB)    // 9 query groups per batch

#define SAMPN   576             // threshold sample = chunk 0
#define NCHUNKB 32
#define CHUNK   (NPIX / NCHUNKB)   // 288 candidates per mask-scan chunk
#define WPC     (CHUNK / 32)       // 9 mask words per chunk
#define NWORDS  (NPIX / 32)        // 288 mask words per query
#define WPL     (NWORDS / 32)      // 9 words per lane in select

#define CBLK    (TOTQ / NTHR)      // 72 blocks (thresh)
#define SWARPS  (NTHR / 32)        // 8 warps per select CTA
#define SBLK    (TOTQ / SWARPS)    // 2304 select blocks

typedef unsigned long long u64;

// Device scratch (allocation-free rule: __device__ globals)
__device__ float4     g_cand[B * NPIX];        // {-2x,-2y,-2z,|c|^2}
__device__ ulonglong2 g_pairA[B * NPIX / 2];   // {x0,x1},{y0,y1} per cand pair
__device__ ulonglong2 g_pairB[B * NPIX / 2];   // {z0,z1},{w0,w1}
__device__ float      g_thr[TOTQ];             // per-query threshold (score)
__device__ unsigned   g_mask[NWORDS][TOTQ];    // survivor bitmask, word-major
__device__ float      g_bsum[SBLK];
__device__ unsigned   g_ticket;                // zero-init; reset after use

// ---- packed helpers -------------------------------------------------------
__device__ __forceinline__ u64 fma2(u64 a, u64 b, u64 c) {
    u64 d;
    asm("fma.rn.f32x2 %0, %1, %2, %3;" : "=l"(d) : "l"(a), "l"(b), "l"(c));
    return d;
}
__device__ __forceinline__ u64 pack2(float lo, float hi) {
    u64 d;
    asm("mov.b64 %0, {%1, %2};" : "=l"(d) : "f"(lo), "f"(hi));
    return d;
}
__device__ __forceinline__ float2 unpack2(u64 v) {
    float2 r;
    asm("mov.b64 {%0, %1}, %2;" : "=f"(r.x), "=f"(r.y) : "l"(v));
    return r;
}

// Scalar compare-exchange insert into sorted-ascending t[0..K-1].
__device__ __forceinline__ void insert8s(float (&t)[K], float u) {
    #pragma unroll
    for (int k = 0; k < K; k++) {
        float lo = fminf(t[k], u);
        u = fmaxf(t[k], u);
        t[k] = lo;
    }
}

// ---------------------------------------------------------------------------
// Kernel 1: pack candidates (plain float4 + pair-interleaved for f32x2)
// ---------------------------------------------------------------------------
__global__ void prep_kernel(const float* __restrict__ in) {
    int idx = blockIdx.x * blockDim.x + threadIdx.x;   // [0, TOTQ)
    if (idx >= TOTQ) return;
    int b = idx / NPIX;
    int i = idx - b * NPIX;
    const float* base = in + (size_t)b * 3 * NPIX;
    float x = base[i];
    float y = base[NPIX + i];
    float z = base[2 * NPIX + i];
    float s = x * x + y * y + z * z;
    float mx = -2.0f * x, my = -2.0f * y, mz = -2.0f * z;
    g_cand[idx] = make_float4(mx, my, mz, s);
    int p = idx >> 1, h = idx & 1;        // NPIX even -> pairs stay in-batch
    float* pa = (float*)&g_pairA[p];
    float* pb = (float*)&g_pairB[p];
    pa[h]     = mx;  pa[2 + h] = my;
    pb[h]     = mz;  pb[2 + h] = s;
}

// ---------------------------------------------------------------------------
// Kernel 2: per-query threshold = 8th-smallest score over chunk 0 (+1 ulp).
// ---------------------------------------------------------------------------
__global__ void __launch_bounds__(NTHR)
thresh_kernel(const float* __restrict__ in) {
    __shared__ float4 sh[SAMPN];   // 9216 B

    int tid = threadIdx.x;
    int q = blockIdx.x * NTHR + tid;     // [0, TOTQ)
    int b = q / NPIX;
    int qi = q - b * NPIX;

    for (int i = tid; i < SAMPN; i += NTHR) sh[i] = g_cand[b * NPIX + i];

    const float* base = in + (size_t)b * 3 * NPIX;
    float ax = base[qi], ay = base[NPIX + qi], az = base[2 * NPIX + qi];

    float t[K];
    #pragma unroll
    for (int k = 0; k < K; k++) t[k] = 3.0e30f;

    __syncthreads();

    for (int j = 0; j < 16; j++) {
        float4 cv = sh[j];
        insert8s(t, fmaf(ax, cv.x, fmaf(ay, cv.y, fmaf(az, cv.z, cv.w))));
    }
    #pragma unroll 4
    for (int j = 16; j < SAMPN; j++) {
        float4 cv = sh[j];
        float d = fmaf(ax, cv.x, fmaf(ay, cv.y, fmaf(az, cv.z, cv.w)));
        if (d < t[K - 1]) insert8s(t, d);
    }
    // strict-< gate downstream must admit d == T -> open the bound one ulp
    g_thr[q] = nextafterf(t[K - 1], 3.4e38f);
}

// ---------------------------------------------------------------------------
// Kernel 3 (HOT): branch-free mask scan with packed FFMA2.
// ---------------------------------------------------------------------------
__global__ void __launch_bounds__(NTHR)
mask_kernel(const float* __restrict__ in) {
    __shared__ ulonglong2 shA[CHUNK / 2];
    __shared__ ulonglong2 shB[CHUNK / 2];

    int bid = blockIdx.x;                 // [0, 576)
    int c   = bid & (NCHUNKB - 1);
    int qg  = (bid >> 5) % NQG;
    int b   = bid / (NQG * NCHUNKB);

    int tid = threadIdx.x;
    int poff = b * (NPIX / 2) + c * (CHUNK / 2);
    for (int i = tid; i < CHUNK / 2; i += NTHR) {
        shA[i] = g_pairA[poff + i];
        shB[i] = g_pairB[poff + i];
    }

    int q0 = qg * QPB + tid;
    int gq = b * NPIX + q0;
    const float* base = in + (size_t)b * 3 * NPIX;
    float a0x = base[q0],            a0y = base[NPIX + q0],            a0z = base[2*NPIX + q0];
    float a1x = base[q0 + NTHR],     a1y = base[NPIX + q0 + NTHR],     a1z = base[2*NPIX + q0 + NTHR];
    float a2x = base[q0 + 2*NTHR],   a2y = base[NPIX + q0 + 2*NTHR],   a2z = base[2*NPIX + q0 + 2*NTHR];
    float a3x = base[q0 + 3*NTHR],   a3y = base[NPIX + q0 + 3*NTHR],   a3z = base[2*NPIX + q0 + 3*NTHR];
    u64 QX0 = pack2(a0x, a0x), QY0 = pack2(a0y, a0y), QZ0 = pack2(a0z, a0z);
    u64 QX1 = pack2(a1x, a1x), QY1 = pack2(a1y, a1y), QZ1 = pack2(a1z, a1z);
    u64 QX2 = pack2(a2x, a2x), QY2 = pack2(a2y, a2y), QZ2 = pack2(a2z, a2z);
    u64 QX3 = pack2(a3x, a3x), QY3 = pack2(a3y, a3y), QZ3 = pack2(a3z, a3z);

    float m0 = g_thr[gq];
    float m1 = g_thr[gq + NTHR];
    float m2 = g_thr[gq + 2 * NTHR];
    float m3 = g_thr[gq + 3 * NTHR];

    __syncthreads();

    for (int s16 = 0; s16 < CHUNK / 2; s16 += 16) {   // 16 pairs = 1 word
        unsigned M0 = 0, M1 = 0, M2 = 0, M3 = 0;
        #pragma unroll
        for (int u = 0; u < 16; u++) {
            ulonglong2 pA = shA[s16 + u];
            ulonglong2 pB = shB[s16 + u];
            u64 d0 = fma2(QX0, pA.x, fma2(QY0, pA.y, fma2(QZ0, pB.x, pB.y)));
            u64 d1 = fma2(QX1, pA.x, fma2(QY1, pA.y, fma2(QZ1, pB.x, pB.y)));
            u64 d2 = fma2(QX2, pA.x, fma2(QY2, pA.y, fma2(QZ2, pB.x, pB.y)));
            u64 d3 = fma2(QX3, pA.x, fma2(QY3, pA.y, fma2(QZ3, pB.x, pB.y)));
            float2 e0 = unpack2(d0);
            float2 e1 = unpack2(d1);
            float2 e2 = unpack2(d2);
            float2 e3 = unpack2(d3);
            if (e0.x < m0) M0 |= (1u << (2 * u));
            if (e0.y < m0) M0 |= (1u << (2 * u + 1));
            if (e1.x < m1) M1 |= (1u << (2 * u));
            if (e1.y < m1) M1 |= (1u << (2 * u + 1));
            if (e2.x < m2) M2 |= (1u << (2 * u));
            if (e2.y < m2) M2 |= (1u << (2 * u + 1));
            if (e3.x < m3) M3 |= (1u << (2 * u));
            if (e3.y < m3) M3 |= (1u << (2 * u + 1));
        }
        int w = c * WPC + (s16 >> 4);
        g_mask[w][gq]            = M0;     // coalesced across threads
        g_mask[w][gq + NTHR]     = M1;
        g_mask[w][gq + 2 * NTHR] = M2;
        g_mask[w][gq + 3 * NTHR] = M3;
    }
}

// ---------------------------------------------------------------------------
// Kernel 4: WARP-PER-QUERY select. Lanes split the 288 mask words, bit-walk
// their own survivors (independent loads, MLP=32), keep lane-local top-8,
// then an 8-step shuffle merge extracts the warp-global 8 smallest.
// Smallest = self distance -> dropped. Fused ticket reduction to scalar.
// ---------------------------------------------------------------------------
__global__ void __launch_bounds__(NTHR)
select_kernel(const float* __restrict__ in, float* __restrict__ out) {
    __shared__ float red[NTHR];
    __shared__ int islast;

    int tid  = threadIdx.x;
    int lane = tid & 31;
    int wid  = tid >> 5;
    int q = blockIdx.x * SWARPS + wid;   // [0, TOTQ)
    int b = q / NPIX;
    int qi = q - b * NPIX;
    const float* base = in + (size_t)b * 3 * NPIX;
    float ax = base[qi], ay = base[NPIX + qi], az = base[2 * NPIX + qi];
    float q2 = fmaf(ax, ax, fmaf(ay, ay, az * az));

    float t[K];
    #pragma unroll
    for (int k = 0; k < K; k++) t[k] = 3.0e30f;

    const float4* cb = g_cand + b * NPIX;
    #pragma unroll
    for (int i = 0; i < WPL; i++) {
        int w = i * 32 + lane;
        unsigned word = g_mask[w][q];
        while (word) {
            int bit = __ffs(word) - 1;
            word &= word - 1;
            float4 cv = cb[w * 32 + bit];
            float d = fmaf(ax, cv.x, fmaf(ay, cv.y, fmaf(az, cv.z, cv.w)));
            if (d < t[K - 1]) insert8s(t, d);
        }
    }

    // 8-step warp merge: global min + ballot-argmin pop
    float s = 0.0f;
    #pragma unroll
    for (int k = 0; k < K; k++) {
        float v = t[0];
        float m = v;
        #pragma unroll
        for (int off = 16; off > 0; off >>= 1)
            m = fminf(m, __shfl_xor_sync(0xFFFFFFFFu, m, off));
        unsigned ball = __ballot_sync(0xFFFFFFFFu, v == m);
        int src = __ffs(ball) - 1;
        if (lane == src) {
            #pragma unroll
            for (int j = 0; j < K - 1; j++) t[j] = t[j + 1];
            t[K - 1] = 3.0e30f;
        }
        // k == 0 is the self-distance (exact 0 in the reference): skip it.
        if (k > 0) s += sqrtf(fmaxf(m + q2, 0.0f));
    }

    if (lane == 0) red[wid] = s;
    __syncthreads();

    // block reduce over SWARPS warp sums
    if (tid == 0) {
        float bs = 0.0f;
        #pragma unroll
        for (int wv = 0; wv < SWARPS; wv++) bs += red[wv];
        g_bsum[blockIdx.x] = bs;
        __threadfence();
        unsigned r = atomicAdd(&g_ticket, 1u);
        islast = (r == (unsigned)(gridDim.x - 1));
    }
    __syncthreads();

    if (islast) {
        float v = 0.0f;
        for (int i = tid; i < SBLK; i += NTHR) v += __ldcg(&g_bsum[i]);
        red[tid] = v;
        __syncthreads();
        #pragma unroll
        for (int w = NTHR / 2; w > 0; w >>= 1) {
            if (tid < w) red[tid] += red[tid + w];
            __syncthreads();
        }
        if (tid == 0) {
            out[0] = -red[0] / (float)(TOTQ * K);
            g_ticket = 0;    // reset for next graph replay
        }
    }
}

extern "C" void kernel_launch(void* const* d_in, const int* in_sizes, int n_in,
                              void* d_out, int out_size) {
    const float* in = (const float*)d_in[0];
    float* out = (float*)d_out;

    prep_kernel<<<(TOTQ + NTHR - 1) / NTHR, NTHR>>>(in);
    thresh_kernel<<<CBLK, NTHR>>>(in);
    mask_kernel<<<B * NQG * NCHUNKB, NTHR>>>(in);
    select_kernel<<<SBLK, NTHR>>>(in, out);
}

// round 11
// speedup vs baseline: 2.9520x; 1.3105x over previous
#include <cuda_runtime.h>
#include <math.h>

// Problem constants: generated [2, 3, 96, 96]
#define B       2
#define NPIX    9216            // 96*96
#define TOTQ    (B * NPIX)      // 18432 queries
#define K       8               // NUM_CLUSTERS
#define NTHR    256
#define QPT     4               // queries per thread (mask kernel)
#define QPB     (NTHR * QPT)    // 1024
#define NQG     (NPIX / QPB)    // 9 query groups per batch

#define SAMPN   576             // threshold sample = chunk 0 (18 per lane)
#define SPL     (SAMPN / 32)    // 18 samples per lane
#define NCHUNKB 32
#define CHUNK   (NPIX / NCHUNKB)   // 288 candidates per mask-scan chunk
#define WPC     (CHUNK / 32)       // 9 mask words per chunk
#define NWORDS  (NPIX / 32)        // 288 mask words per query
#define WPL     (NWORDS / 32)      // 9 consecutive words per lane in select

#define SWARPS  (NTHR / 32)        // 8 warps per CTA (thresh/select)
#define SBLK    (TOTQ / SWARPS)    // 2304 blocks

typedef unsigned long long u64;

// Device scratch (allocation-free rule: __device__ globals)
__device__ float4     g_cand[B * NPIX];        // {-2x,-2y,-2z,|c|^2}
__device__ ulonglong2 g_pairA[B * NPIX / 2];   // {x0,x1},{y0,y1} per cand pair
__device__ ulonglong2 g_pairB[B * NPIX / 2];   // {z0,z1},{w0,w1}
__device__ float      g_thr[TOTQ];             // per-query threshold (score)
__device__ unsigned   g_mask[NWORDS][TOTQ];    // survivor bitmask, word-major
__device__ float      g_bsum[SBLK];
__device__ unsigned   g_ticket;                // zero-init; reset after use

// ---- packed helpers -------------------------------------------------------
__device__ __forceinline__ u64 fma2(u64 a, u64 b, u64 c) {
    u64 d;
    asm("fma.rn.f32x2 %0, %1, %2, %3;" : "=l"(d) : "l"(a), "l"(b), "l"(c));
    return d;
}
__device__ __forceinline__ u64 pack2(float lo, float hi) {
    u64 d;
    asm("mov.b64 %0, {%1, %2};" : "=l"(d) : "f"(lo), "f"(hi));
    return d;
}
__device__ __forceinline__ float2 unpack2(u64 v) {
    float2 r;
    asm("mov.b64 {%0, %1}, %2;" : "=f"(r.x), "=f"(r.y) : "l"(v));
    return r;
}

// Scalar compare-exchange insert into sorted-ascending t[0..K-1].
__device__ __forceinline__ void insert8s(float (&t)[K], float u) {
    #pragma unroll
    for (int k = 0; k < K; k++) {
        float lo = fminf(t[k], u);
        u = fmaxf(t[k], u);
        t[k] = lo;
    }
}

// ---------------------------------------------------------------------------
// Kernel 1: pack candidates (plain float4 + pair-interleaved for f32x2)
// ---------------------------------------------------------------------------
__global__ void prep_kernel(const float* __restrict__ in) {
    int idx = blockIdx.x * blockDim.x + threadIdx.x;   // [0, TOTQ)
    if (idx >= TOTQ) return;
    int b = idx / NPIX;
    int i = idx - b * NPIX;
    const float* base = in + (size_t)b * 3 * NPIX;
    float x = base[i];
    float y = base[NPIX + i];
    float z = base[2 * NPIX + i];
    float s = x * x + y * y + z * z;
    float mx = -2.0f * x, my = -2.0f * y, mz = -2.0f * z;
    g_cand[idx] = make_float4(mx, my, mz, s);
    int p = idx >> 1, h = idx & 1;        // NPIX even -> pairs stay in-batch
    float* pa = (float*)&g_pairA[p];
    float* pb = (float*)&g_pairB[p];
    pa[h]     = mx;  pa[2 + h] = my;
    pb[h]     = mz;  pb[2 + h] = s;
}

// ---------------------------------------------------------------------------
// Kernel 2: WARP-PER-QUERY threshold, divergence-free.
// Each lane tracks the 2 smallest of its 18 sample scores; T = 8th smallest
// of the 64 lane-top-2 values (valid upper bound on the sample 8th: the 8
// extracted entries are genuine scores <= T). +1 ulp for the strict-< gate.
// ---------------------------------------------------------------------------
__global__ void __launch_bounds__(NTHR)
thresh_kernel(const float* __restrict__ in) {
    int tid  = threadIdx.x;
    int lane = tid & 31;
    int wid  = tid >> 5;
    int q = blockIdx.x * SWARPS + wid;   // [0, TOTQ)
    int b = q / NPIX;
    int qi = q - b * NPIX;
    const float* base = in + (size_t)b * 3 * NPIX;
    float ax = base[qi], ay = base[NPIX + qi], az = base[2 * NPIX + qi];

    const float4* cb = g_cand + b * NPIX;
    float m1 = 3.0e30f, m2 = 3.0e30f;    // two smallest seen by this lane
    #pragma unroll
    for (int i = 0; i < SPL; i++) {
        float4 cv = cb[i * 32 + lane];   // coalesced; table L1-hot
        float d = fmaf(ax, cv.x, fmaf(ay, cv.y, fmaf(az, cv.z, cv.w)));
        float lo = fminf(m1, d);
        float hi = fmaxf(m1, d);
        m1 = lo;
        m2 = fminf(m2, hi);
    }

    // extract 8 smallest of the 64 {m1,m2} values; T = the 8th
    float v = m1;
    float T = 3.0e30f;
    #pragma unroll
    for (int k = 0; k < K; k++) {
        float m = v;
        #pragma unroll
        for (int off = 16; off > 0; off >>= 1)
            m = fminf(m, __shfl_xor_sync(0xFFFFFFFFu, m, off));
        unsigned ball = __ballot_sync(0xFFFFFFFFu, v == m);
        int src = __ffs(ball) - 1;
        if (lane == src) { v = m2; m2 = 3.0e30f; }
        T = m;
    }
    if (lane == 0) g_thr[q] = nextafterf(T, 3.4e38f);
}

// ---------------------------------------------------------------------------
// Kernel 3 (HOT): branch-free mask scan with packed FFMA2.
// ---------------------------------------------------------------------------
__global__ void __launch_bounds__(NTHR)
mask_kernel(const float* __restrict__ in) {
    __shared__ ulonglong2 shA[CHUNK / 2];
    __shared__ ulonglong2 shB[CHUNK / 2];

    int bid = blockIdx.x;                 // [0, 576)
    int c   = bid & (NCHUNKB - 1);
    int qg  = (bid >> 5) % NQG;
    int b   = bid / (NQG * NCHUNKB);

    int tid = threadIdx.x;
    int poff = b * (NPIX / 2) + c * (CHUNK / 2);
    for (int i = tid; i < CHUNK / 2; i += NTHR) {
        shA[i] = g_pairA[poff + i];
        shB[i] = g_pairB[poff + i];
    }

    int q0 = qg * QPB + tid;
    int gq = b * NPIX + q0;
    const float* base = in + (size_t)b * 3 * NPIX;
    float a0x = base[q0],            a0y = base[NPIX + q0],            a0z = base[2*NPIX + q0];
    float a1x = base[q0 + NTHR],     a1y = base[NPIX + q0 + NTHR],     a1z = base[2*NPIX + q0 + NTHR];
    float a2x = base[q0 + 2*NTHR],   a2y = base[NPIX + q0 + 2*NTHR],   a2z = base[2*NPIX + q0 + 2*NTHR];
    float a3x = base[q0 + 3*NTHR],   a3y = base[NPIX + q0 + 3*NTHR],   a3z = base[2*NPIX + q0 + 3*NTHR];
    u64 QX0 = pack2(a0x, a0x), QY0 = pack2(a0y, a0y), QZ0 = pack2(a0z, a0z);
    u64 QX1 = pack2(a1x, a1x), QY1 = pack2(a1y, a1y), QZ1 = pack2(a1z, a1z);
    u64 QX2 = pack2(a2x, a2x), QY2 = pack2(a2y, a2y), QZ2 = pack2(a2z, a2z);
    u64 QX3 = pack2(a3x, a3x), QY3 = pack2(a3y, a3y), QZ3 = pack2(a3z, a3z);

    float m0 = g_thr[gq];
    float m1 = g_thr[gq + NTHR];
    float m2 = g_thr[gq + 2 * NTHR];
    float m3 = g_thr[gq + 3 * NTHR];

    __syncthreads();

    for (int s16 = 0; s16 < CHUNK / 2; s16 += 16) {   // 16 pairs = 1 word
        unsigned M0 = 0, M1 = 0, M2 = 0, M3 = 0;
        #pragma unroll
        for (int u = 0; u < 16; u++) {
            ulonglong2 pA = shA[s16 + u];
            ulonglong2 pB = shB[s16 + u];
            u64 d0 = fma2(QX0, pA.x, fma2(QY0, pA.y, fma2(QZ0, pB.x, pB.y)));
            u64 d1 = fma2(QX1, pA.x, fma2(QY1, pA.y, fma2(QZ1, pB.x, pB.y)));
            u64 d2 = fma2(QX2, pA.x, fma2(QY2, pA.y, fma2(QZ2, pB.x, pB.y)));
            u64 d3 = fma2(QX3, pA.x, fma2(QY3, pA.y, fma2(QZ3, pB.x, pB.y)));
            float2 e0 = unpack2(d0);
            float2 e1 = unpack2(d1);
            float2 e2 = unpack2(d2);
            float2 e3 = unpack2(d3);
            if (e0.x < m0) M0 |= (1u << (2 * u));
            if (e0.y < m0) M0 |= (1u << (2 * u + 1));
            if (e1.x < m1) M1 |= (1u << (2 * u));
            if (e1.y < m1) M1 |= (1u << (2 * u + 1));
            if (e2.x < m2) M2 |= (1u << (2 * u));
            if (e2.y < m2) M2 |= (1u << (2 * u + 1));
            if (e3.x < m3) M3 |= (1u << (2 * u));
            if (e3.y < m3) M3 |= (1u << (2 * u + 1));
        }
        int w = c * WPC + (s16 >> 4);
        g_mask[w][gq]            = M0;     // coalesced across threads
        g_mask[w][gq + NTHR]     = M1;
        g_mask[w][gq + 2 * NTHR] = M2;
        g_mask[w][gq + 3 * NTHR] = M3;
    }
}

// ---------------------------------------------------------------------------
// Kernel 4: WARP-PER-QUERY select with smem-staged masks and a flattened
// per-lane survivor stream (one divergent loop instead of 9).
// ---------------------------------------------------------------------------
__global__ void __launch_bounds__(NTHR)
select_kernel(const float* __restrict__ in, float* __restrict__ out) {
    __shared__ unsigned smask[SWARPS][NWORDS + 1];   // +1 pad kills conflicts
    __shared__ float red[SWARPS];
    __shared__ int islast;

    int tid  = threadIdx.x;
    int lane = tid & 31;
    int wid  = tid >> 5;
    int qbase = blockIdx.x * SWARPS;

    // coalesced mask staging: 32B runs of 8 queries per word
    for (int idx = tid; idx < SWARPS * NWORDS; idx += NTHR) {
        int w = idx >> 3;
        int j = idx & (SWARPS - 1);
        smask[j][w] = g_mask[w][qbase + j];
    }

    int q = qbase + wid;
    int b = q / NPIX;
    int qi = q - b * NPIX;
    const float* base = in + (size_t)b * 3 * NPIX;
    float ax = base[qi], ay = base[NPIX + qi], az = base[2 * NPIX + qi];
    float q2 = fmaf(ax, ax, fmaf(ay, ay, az * az));

    float t[K];
    #pragma unroll
    for (int k = 0; k < K; k++) t[k] = 3.0e30f;

    __syncthreads();

    // flattened survivor stream over this lane's 9 consecutive words
    const unsigned* mw = smask[wid];
    const float4* cb = g_cand + b * NPIX;
    int wi   = lane * WPL;
    int wend = wi + WPL;
    unsigned word = mw[wi];
    for (;;) {
        while (word == 0 && wi + 1 < wend) { wi++; word = mw[wi]; }
        if (word == 0) break;
        int bit = __ffs(word) - 1;
        word &= word - 1;
        float4 cv = cb[wi * 32 + bit];
        float d = fmaf(ax, cv.x, fmaf(ay, cv.y, fmaf(az, cv.z, cv.w)));
        insert8s(t, d);
    }

    // 8-step warp merge: global min + ballot-argmin pop
    float s = 0.0f;
    #pragma unroll
    for (int k = 0; k < K; k++) {
        float v = t[0];
        float m = v;
        #pragma unroll
        for (int off = 16; off > 0; off >>= 1)
            m = fminf(m, __shfl_xor_sync(0xFFFFFFFFu, m, off));
        unsigned ball = __ballot_sync(0xFFFFFFFFu, v == m);
        int src = __ffs(ball) - 1;
        if (lane == src) {
            #pragma unroll
            for (int j = 0; j < K - 1; j++) t[j] = t[j + 1];
            t[K - 1] = 3.0e30f;
        }
        // k == 0 is the self-distance (exact 0 in the reference): skip it.
        if (k > 0) s += sqrtf(fmaxf(m + q2, 0.0f));
    }

    if (lane == 0) red[wid] = s;
    __syncthreads();

    if (tid == 0) {
        float bs = 0.0f;
        #pragma unroll
        for (int wv = 0; wv < SWARPS; wv++) bs += red[wv];
        g_bsum[blockIdx.x] = bs;
        __threadfence();
        unsigned r = atomicAdd(&g_ticket, 1u);
        islast = (r == (unsigned)(gridDim.x - 1));
    }
    __syncthreads();

    if (islast) {
        __shared__ float red2[NTHR];
        float v = 0.0f;
        for (int i = tid; i < SBLK; i += NTHR) v += __ldcg(&g_bsum[i]);
        red2[tid] = v;
        __syncthreads();
        #pragma unroll
        for (int w = NTHR / 2; w > 0; w >>= 1) {
            if (tid < w) red2[tid] += red2[tid + w];
            __syncthreads();
        }
        if (tid == 0) {
            out[0] = -red2[0] / (float)(TOTQ * K);
            g_ticket = 0;    // reset for next graph replay
        }
    }
}

extern "C" void kernel_launch(void* const* d_in, const int* in_sizes, int n_in,
                              void* d_out, int out_size) {
    const float* in = (const float*)d_in[0];
    float* out = (float*)d_out;

    prep_kernel<<<(TOTQ + NTHR - 1) / NTHR, NTHR>>>(in);
    thresh_kernel<<<SBLK, NTHR>>>(in);
    mask_kernel<<<B * NQG * NCHUNKB, NTHR>>>(in);
    select_kernel<<<SBLK, NTHR>>>(in, out);
}

// round 12
// speedup vs baseline: 3.1651x; 1.0722x over previous
#include <cuda_runtime.h>
#include <math.h>

// Problem constants: generated [2, 3, 96, 96]
#define B       2
#define NPIX    9216            // 96*96
#define TOTQ    (B * NPIX)      // 18432 queries
#define K       8               // NUM_CLUSTERS
#define NTHR    256
#define QPT     4               // queries per thread (mask kernel)
#define QPB     (NTHR * QPT)    // 1024
#define NQG     (NPIX / QPB)    // 9 query groups per batch

#define SAMPN   1152            // threshold sample = first 1152 candidates
#define SPL     (SAMPN / 32)    // 36 samples per lane
#define NCHUNKB 32
#define CHUNK   (NPIX / NCHUNKB)   // 288 candidates per mask-scan chunk
#define WPC     (CHUNK / 32)       // 9 mask words per chunk
#define NWORDS  (NPIX / 32)        // 288 mask words per query
#define WPL     (NWORDS / 32)      // 9 consecutive words per lane in select

#define SWARPS  (NTHR / 32)        // 8 warps per CTA (thresh/select)
#define SBLK    (TOTQ / SWARPS)    // 2304 blocks
#define QCAP    256                // survivor queue capacity per query

typedef unsigned long long u64;

// Device scratch (allocation-free rule: __device__ globals)
__device__ float4     g_cand[B * NPIX];        // {-2x,-2y,-2z,|c|^2}
__device__ ulonglong2 g_pairA[B * NPIX / 2];   // {x0,x1},{y0,y1} per cand pair
__device__ ulonglong2 g_pairB[B * NPIX / 2];   // {z0,z1},{w0,w1}
__device__ float      g_thr[TOTQ];             // per-query threshold (score)
__device__ unsigned   g_mask[NWORDS][TOTQ];    // survivor bitmask, word-major
__device__ float      g_bsum[SBLK];
__device__ unsigned   g_ticket;                // zero-init; reset after use

// ---- packed helpers -------------------------------------------------------
__device__ __forceinline__ u64 fma2(u64 a, u64 b, u64 c) {
    u64 d;
    asm("fma.rn.f32x2 %0, %1, %2, %3;" : "=l"(d) : "l"(a), "l"(b), "l"(c));
    return d;
}
__device__ __forceinline__ u64 pack2(float lo, float hi) {
    u64 d;
    asm("mov.b64 %0, {%1, %2};" : "=l"(d) : "f"(lo), "f"(hi));
    return d;
}
__device__ __forceinline__ float2 unpack2(u64 v) {
    float2 r;
    asm("mov.b64 {%0, %1}, %2;" : "=f"(r.x), "=f"(r.y) : "l"(v));
    return r;
}

// Scalar compare-exchange insert into sorted-ascending t[0..K-1].
__device__ __forceinline__ void insert8s(float (&t)[K], float u) {
    #pragma unroll
    for (int k = 0; k < K; k++) {
        float lo = fminf(t[k], u);
        u = fmaxf(t[k], u);
        t[k] = lo;
    }
}

// ---------------------------------------------------------------------------
// Kernel 1: pack candidates (plain float4 + pair-interleaved for f32x2)
// ---------------------------------------------------------------------------
__global__ void prep_kernel(const float* __restrict__ in) {
    int idx = blockIdx.x * blockDim.x + threadIdx.x;   // [0, TOTQ)
    if (idx >= TOTQ) return;
    int b = idx / NPIX;
    int i = idx - b * NPIX;
    const float* base = in + (size_t)b * 3 * NPIX;
    float x = base[i];
    float y = base[NPIX + i];
    float z = base[2 * NPIX + i];
    float s = x * x + y * y + z * z;
    float mx = -2.0f * x, my = -2.0f * y, mz = -2.0f * z;
    g_cand[idx] = make_float4(mx, my, mz, s);
    int p = idx >> 1, h = idx & 1;        // NPIX even -> pairs stay in-batch
    float* pa = (float*)&g_pairA[p];
    float* pb = (float*)&g_pairB[p];
    pa[h]     = mx;  pa[2 + h] = my;
    pb[h]     = mz;  pb[2 + h] = s;
}

// ---------------------------------------------------------------------------
// Kernel 2: WARP-PER-QUERY threshold, divergence-free.
// Each lane keeps the 2 smallest of its 36 sample scores; T = 8th smallest
// of the 64 lane values (>= 8 genuine scores <= T => T >= global 8th).
// ---------------------------------------------------------------------------
__global__ void __launch_bounds__(NTHR)
thresh_kernel(const float* __restrict__ in) {
    int tid  = threadIdx.x;
    int lane = tid & 31;
    int wid  = tid >> 5;
    int q = blockIdx.x * SWARPS + wid;   // [0, TOTQ)
    int b = q / NPIX;
    int qi = q - b * NPIX;
    const float* base = in + (size_t)b * 3 * NPIX;
    float ax = base[qi], ay = base[NPIX + qi], az = base[2 * NPIX + qi];

    const float4* cb = g_cand + b * NPIX;
    // two independent accumulator pairs to shorten the min dependency chain
    float p1 = 3.0e30f, p2 = 3.0e30f, r1 = 3.0e30f, r2 = 3.0e30f;
    #pragma unroll 4
    for (int i = 0; i < SPL; i += 2) {
        float4 cv = cb[i * 32 + lane];        // coalesced; L1-hot per CTA
        float d = fmaf(ax, cv.x, fmaf(ay, cv.y, fmaf(az, cv.z, cv.w)));
        float lo = fminf(p1, d), hi = fmaxf(p1, d);
        p1 = lo; p2 = fminf(p2, hi);
        float4 cw = cb[(i + 1) * 32 + lane];
        float e = fmaf(ax, cw.x, fmaf(ay, cw.y, fmaf(az, cw.z, cw.w)));
        lo = fminf(r1, e); hi = fmaxf(r1, e);
        r1 = lo; r2 = fminf(r2, hi);
    }
    // merge pairs -> lane top-2
    float m1 = fminf(p1, r1);
    float mm = fmaxf(p1, r1);
    float m2 = fminf(fminf(p2, r2), mm);

    // extract 8 smallest of the 64 {m1,m2}; T = the 8th
    float v = m1;
    float T = 3.0e30f;
    #pragma unroll
    for (int k = 0; k < K; k++) {
        float m = v;
        #pragma unroll
        for (int off = 16; off > 0; off >>= 1)
            m = fminf(m, __shfl_xor_sync(0xFFFFFFFFu, m, off));
        unsigned ball = __ballot_sync(0xFFFFFFFFu, v == m);
        int src = __ffs(ball) - 1;
        if (lane == src) { v = m2; m2 = 3.0e30f; }
        T = m;
    }
    if (lane == 0) g_thr[q] = nextafterf(T, 3.4e38f);
}

// ---------------------------------------------------------------------------
// Kernel 3 (HOT): branch-free mask scan with packed FFMA2.
// ---------------------------------------------------------------------------
__global__ void __launch_bounds__(NTHR)
mask_kernel(const float* __restrict__ in) {
    __shared__ ulonglong2 shA[CHUNK / 2];
    __shared__ ulonglong2 shB[CHUNK / 2];

    int bid = blockIdx.x;                 // [0, 576)
    int c   = bid & (NCHUNKB - 1);
    int qg  = (bid >> 5) % NQG;
    int b   = bid / (NQG * NCHUNKB);

    int tid = threadIdx.x;
    int poff = b * (NPIX / 2) + c * (CHUNK / 2);
    for (int i = tid; i < CHUNK / 2; i += NTHR) {
        shA[i] = g_pairA[poff + i];
        shB[i] = g_pairB[poff + i];
    }

    int q0 = qg * QPB + tid;
    int gq = b * NPIX + q0;
    const float* base = in + (size_t)b * 3 * NPIX;
    float a0x = base[q0],            a0y = base[NPIX + q0],            a0z = base[2*NPIX + q0];
    float a1x = base[q0 + NTHR],     a1y = base[NPIX + q0 + NTHR],     a1z = base[2*NPIX + q0 + NTHR];
    float a2x = base[q0 + 2*NTHR],   a2y = base[NPIX + q0 + 2*NTHR],   a2z = base[2*NPIX + q0 + 2*NTHR];
    float a3x = base[q0 + 3*NTHR],   a3y = base[NPIX + q0 + 3*NTHR],   a3z = base[2*NPIX + q0 + 3*NTHR];
    u64 QX0 = pack2(a0x, a0x), QY0 = pack2(a0y, a0y), QZ0 = pack2(a0z, a0z);
    u64 QX1 = pack2(a1x, a1x), QY1 = pack2(a1y, a1y), QZ1 = pack2(a1z, a1z);
    u64 QX2 = pack2(a2x, a2x), QY2 = pack2(a2y, a2y), QZ2 = pack2(a2z, a2z);
    u64 QX3 = pack2(a3x, a3x), QY3 = pack2(a3y, a3y), QZ3 = pack2(a3z, a3z);

    float m0 = g_thr[gq];
    float m1 = g_thr[gq + NTHR];
    float m2 = g_thr[gq + 2 * NTHR];
    float m3 = g_thr[gq + 3 * NTHR];

    __syncthreads();

    for (int s16 = 0; s16 < CHUNK / 2; s16 += 16) {   // 16 pairs = 1 word
        unsigned M0 = 0, M1 = 0, M2 = 0, M3 = 0;
        #pragma unroll
        for (int u = 0; u < 16; u++) {
            ulonglong2 pA = shA[s16 + u];
            ulonglong2 pB = shB[s16 + u];
            u64 d0 = fma2(QX0, pA.x, fma2(QY0, pA.y, fma2(QZ0, pB.x, pB.y)));
            u64 d1 = fma2(QX1, pA.x, fma2(QY1, pA.y, fma2(QZ1, pB.x, pB.y)));
            u64 d2 = fma2(QX2, pA.x, fma2(QY2, pA.y, fma2(QZ2, pB.x, pB.y)));
            u64 d3 = fma2(QX3, pA.x, fma2(QY3, pA.y, fma2(QZ3, pB.x, pB.y)));
            float2 e0 = unpack2(d0);
            float2 e1 = unpack2(d1);
            float2 e2 = unpack2(d2);
            float2 e3 = unpack2(d3);
            if (e0.x < m0) M0 |= (1u << (2 * u));
            if (e0.y < m0) M0 |= (1u << (2 * u + 1));
            if (e1.x < m1) M1 |= (1u << (2 * u));
            if (e1.y < m1) M1 |= (1u << (2 * u + 1));
            if (e2.x < m2) M2 |= (1u << (2 * u));
            if (e2.y < m2) M2 |= (1u << (2 * u + 1));
            if (e3.x < m3) M3 |= (1u << (2 * u));
            if (e3.y < m3) M3 |= (1u << (2 * u + 1));
        }
        int w = c * WPC + (s16 >> 4);
        g_mask[w][gq]            = M0;     // coalesced across threads
        g_mask[w][gq + NTHR]     = M1;
        g_mask[w][gq + 2 * NTHR] = M2;
        g_mask[w][gq + 3 * NTHR] = M3;
    }
}

// ---------------------------------------------------------------------------
// Kernel 4: WARP-PER-QUERY select. Masks staged to smem; survivors compacted
// (popc + shfl-scan + u16 index queue) then processed 32-wide and balanced.
// Overflow (> QCAP, ~never) falls back to the exact per-lane bit-walk.
// ---------------------------------------------------------------------------
__global__ void __launch_bounds__(NTHR)
select_kernel(const float* __restrict__ in, float* __restrict__ out) {
    __shared__ unsigned smask[SWARPS][NWORDS + 1];      // +1 pad
    __shared__ unsigned short squeue[SWARPS][QCAP];
    __shared__ float red[SWARPS];
    __shared__ int islast;

    int tid  = threadIdx.x;
    int lane = tid & 31;
    int wid  = tid >> 5;
    int qbase = blockIdx.x * SWARPS;

    // coalesced mask staging: 32B runs of 8 queries per word
    for (int idx = tid; idx < SWARPS * NWORDS; idx += NTHR) {
        int w = idx >> 3;
        int j = idx & (SWARPS - 1);
        smask[j][w] = g_mask[w][qbase + j];
    }

    int q = qbase + wid;
    int b = q / NPIX;
    int qi = q - b * NPIX;
    const float* base = in + (size_t)b * 3 * NPIX;
    float ax = base[qi], ay = base[NPIX + qi], az = base[2 * NPIX + qi];
    float q2 = fmaf(ax, ax, fmaf(ay, ay, az * az));

    float t[K];
    #pragma unroll
    for (int k = 0; k < K; k++) t[k] = 3.0e30f;

    __syncthreads();

    const unsigned* mw = smask[wid];
    const float4* cb = g_cand + b * NPIX;
    int w0 = lane * WPL;

    // lane survivor count + warp exclusive scan
    unsigned nl = 0;
    #pragma unroll
    for (int i = 0; i < WPL; i++) nl += __popc(mw[w0 + i]);
    unsigned pfx = nl;
    #pragma unroll
    for (int off = 1; off < 32; off <<= 1) {
        unsigned v = __shfl_up_sync(0xFFFFFFFFu, pfx, off);
        if (lane >= off) pfx += v;
    }
    unsigned total = __shfl_sync(0xFFFFFFFFu, pfx, 31);
    pfx -= nl;   // exclusive prefix

    if (total <= QCAP) {
        // compact survivor candidate-indices (cheap bodies; imbalance ok)
        int pos = pfx;
        #pragma unroll
        for (int i = 0; i < WPL; i++) {
            unsigned word = mw[w0 + i];
            while (word) {
                int bit = __ffs(word) - 1;
                word &= word - 1;
                squeue[wid][pos++] = (unsigned short)((w0 + i) * 32 + bit);
            }
        }
        __syncwarp();
        // balanced 32-wide processing with full MLP
        for (unsigned bb = 0; bb < total; bb += 32) {
            unsigned ii = bb + lane;
            float d = 3.0e30f;
            if (ii < total) {
                float4 cv = cb[squeue[wid][ii]];
                d = fmaf(ax, cv.x, fmaf(ay, cv.y, fmaf(az, cv.z, cv.w)));
            }
            insert8s(t, d);
        }
    } else {
        // exact fallback: per-lane flattened bit-walk (R11 path)
        int wi = w0, wend = w0 + WPL;
        unsigned word = mw[wi];
        for (;;) {
            while (word == 0 && wi + 1 < wend) { wi++; word = mw[wi]; }
            if (word == 0) break;
            int bit = __ffs(word) - 1;
            word &= word - 1;
            float4 cv = cb[wi * 32 + bit];
            float d = fmaf(ax, cv.x, fmaf(ay, cv.y, fmaf(az, cv.z, cv.w)));
            insert8s(t, d);
        }
    }

    // 8-step warp merge: global min + ballot-argmin pop
    float s = 0.0f;
    #pragma unroll
    for (int k = 0; k < K; k++) {
        float v = t[0];
        float m = v;
        #pragma unroll
        for (int off = 16; off > 0; off >>= 1)
            m = fminf(m, __shfl_xor_sync(0xFFFFFFFFu, m, off));
        unsigned ball = __ballot_sync(0xFFFFFFFFu, v == m);
        int src = __ffs(ball) - 1;
        if (lane == src) {
            #pragma unroll
            for (int j = 0; j < K - 1; j++) t[j] = t[j + 1];
            t[K - 1] = 3.0e30f;
        }
        // k == 0 is the self-distance (exact 0 in the reference): skip it.
        if (k > 0) s += sqrtf(fmaxf(m + q2, 0.0f));
    }

    if (lane == 0) red[wid] = s;
    __syncthreads();

    if (tid == 0) {
        float bs = 0.0f;
        #pragma unroll
        for (int wv = 0; wv < SWARPS; wv++) bs += red[wv];
        g_bsum[blockIdx.x] = bs;
        __threadfence();
        unsigned r = atomicAdd(&g_ticket, 1u);
        islast = (r == (unsigned)(gridDim.x - 1));
    }
    __syncthreads();

    if (islast) {
        __shared__ float red2[NTHR];
        float v = 0.0f;
        for (int i = tid; i < SBLK; i += NTHR) v += __ldcg(&g_bsum[i]);
        red2[tid] = v;
        __syncthreads();
        #pragma unroll
        for (int w = NTHR / 2; w > 0; w >>= 1) {
            if (tid < w) red2[tid] += red2[tid + w];
            __syncthreads();
        }
        if (tid == 0) {
            out[0] = -red2[0] / (float)(TOTQ * K);
            g_ticket = 0;    // reset for next graph replay
        }
    }
}

extern "C" void kernel_launch(void* const* d_in, const int* in_sizes, int n_in,
                              void* d_out, int out_size) {
    const float* in = (const float*)d_in[0];
    float* out = (float*)d_out;

    prep_kernel<<<(TOTQ + NTHR - 1) / NTHR, NTHR>>>(in);
    thresh_kernel<<<SBLK, NTHR>>>(in);
    mask_kernel<<<B * NQG * NCHUNKB, NTHR>>>(in);
    select_kernel<<<SBLK, NTHR>>>(in, out);
}

// round 13
// speedup vs baseline: 3.1854x; 1.0064x over previous
#include <cuda_runtime.h>
#include <math.h>

// Problem constants: generated [2, 3, 96, 96]
#define B       2
#define NPIX    9216            // 96*96
#define TOTQ    (B * NPIX)      // 18432 queries
#define K       8               // NUM_CLUSTERS
#define NTHR    256
#define QPT     4               // queries per thread (mask kernel)
#define QPB     (NTHR * QPT)    // 1024
#define NQG     (NPIX / QPB)    // 9 query groups per batch

#define SAMPN   1152            // threshold sample = first 1152 candidates
#define SPL     (SAMPN / 32)    // 36 samples per lane
#define NCHUNKB 32
#define CHUNK   (NPIX / NCHUNKB)   // 288 candidates per mask-scan chunk
#define WPC     (CHUNK / 32)       // 9 mask words per chunk
#define NWORDS  (NPIX / 32)        // 288 mask words per query
#define WPL     (NWORDS / 32)      // 9 consecutive words per lane in select

#define SWARPS  (NTHR / 32)        // 8 warps per CTA (thresh/select)
#define SBLK    (TOTQ / SWARPS)    // 2304 blocks
#define QCAP    128                // survivor queue capacity (primary path)

typedef unsigned long long u64;

// Device scratch (allocation-free rule: __device__ globals)
__device__ float4     g_cand[B * NPIX];        // {-2x,-2y,-2z,|c|^2}
__device__ ulonglong2 g_pairA[B * NPIX / 2];   // {x0,x1},{y0,y1} per cand pair
__device__ ulonglong2 g_pairB[B * NPIX / 2];   // {z0,z1},{w0,w1}
__device__ float      g_thr[TOTQ];             // per-query threshold (score)
__device__ unsigned   g_mask[NWORDS][TOTQ];    // survivor bitmask, word-major
__device__ float      g_bsum[SBLK];
__device__ unsigned   g_ticket;                // zero-init; reset after use

// ---- packed helpers -------------------------------------------------------
__device__ __forceinline__ u64 fma2(u64 a, u64 b, u64 c) {
    u64 d;
    asm("fma.rn.f32x2 %0, %1, %2, %3;" : "=l"(d) : "l"(a), "l"(b), "l"(c));
    return d;
}
__device__ __forceinline__ u64 pack2(float lo, float hi) {
    u64 d;
    asm("mov.b64 %0, {%1, %2};" : "=l"(d) : "f"(lo), "f"(hi));
    return d;
}
__device__ __forceinline__ float2 unpack2(u64 v) {
    float2 r;
    asm("mov.b64 {%0, %1}, %2;" : "=f"(r.x), "=f"(r.y) : "l"(v));
    return r;
}

// Order-preserving float -> unsigned map (total order, asc) and inverse.
__device__ __forceinline__ unsigned mapf(float d) {
    int b = __float_as_int(d);
    return (unsigned)(b ^ ((b >> 31) | 0x80000000));
}
__device__ __forceinline__ float unmapf(unsigned u) {
    int s = (int)u >> 31;   // arithmetic
    unsigned m = (~(unsigned)s) | 0x80000000u;
    return __int_as_float((int)(u ^ m));
}

// Scalar compare-exchange insert into sorted-ascending t[0..K-1] (floats).
__device__ __forceinline__ void insert8s(float (&t)[K], float u) {
    #pragma unroll
    for (int k = 0; k < K; k++) {
        float lo = fminf(t[k], u);
        u = fmaxf(t[k], u);
        t[k] = lo;
    }
}

// 4-deep unsigned insert (primary select path; <=4 inserts per lane).
__device__ __forceinline__ void insert4u(unsigned (&t)[4], unsigned u) {
    #pragma unroll
    for (int k = 0; k < 4; k++) {
        unsigned lo = min(t[k], u);
        u = max(t[k], u);
        t[k] = lo;
    }
}

// ---------------------------------------------------------------------------
// Kernel 1: pack candidates (plain float4 + pair-interleaved for f32x2)
// ---------------------------------------------------------------------------
__global__ void prep_kernel(const float* __restrict__ in) {
    int idx = blockIdx.x * blockDim.x + threadIdx.x;   // [0, TOTQ)
    if (idx >= TOTQ) return;
    int b = idx / NPIX;
    int i = idx - b * NPIX;
    const float* base = in + (size_t)b * 3 * NPIX;
    float x = base[i];
    float y = base[NPIX + i];
    float z = base[2 * NPIX + i];
    float s = x * x + y * y + z * z;
    float mx = -2.0f * x, my = -2.0f * y, mz = -2.0f * z;
    g_cand[idx] = make_float4(mx, my, mz, s);
    int p = idx >> 1, h = idx & 1;        // NPIX even -> pairs stay in-batch
    float* pa = (float*)&g_pairA[p];
    float* pb = (float*)&g_pairB[p];
    pa[h]     = mx;  pa[2 + h] = my;
    pb[h]     = mz;  pb[2 + h] = s;
}

// ---------------------------------------------------------------------------
// Kernel 2: WARP-PER-QUERY threshold, divergence-free.
// Each lane keeps the 2 smallest of its 36 sample scores; T = 8th smallest
// of the 64 lane values (>= 8 genuine scores <= T => T >= global 8th).
// ---------------------------------------------------------------------------
__global__ void __launch_bounds__(NTHR)
thresh_kernel(const float* __restrict__ in) {
    int tid  = threadIdx.x;
    int lane = tid & 31;
    int wid  = tid >> 5;
    int q = blockIdx.x * SWARPS + wid;   // [0, TOTQ)
    int b = q / NPIX;
    int qi = q - b * NPIX;
    const float* base = in + (size_t)b * 3 * NPIX;
    float ax = base[qi], ay = base[NPIX + qi], az = base[2 * NPIX + qi];

    const float4* cb = g_cand + b * NPIX;
    float p1 = 3.0e30f, p2 = 3.0e30f, r1 = 3.0e30f, r2 = 3.0e30f;
    #pragma unroll 4
    for (int i = 0; i < SPL; i += 2) {
        float4 cv = cb[i * 32 + lane];        // coalesced; L1-hot per CTA
        float d = fmaf(ax, cv.x, fmaf(ay, cv.y, fmaf(az, cv.z, cv.w)));
        float lo = fminf(p1, d), hi = fmaxf(p1, d);
        p1 = lo; p2 = fminf(p2, hi);
        float4 cw = cb[(i + 1) * 32 + lane];
        float e = fmaf(ax, cw.x, fmaf(ay, cw.y, fmaf(az, cw.z, cw.w)));
        lo = fminf(r1, e); hi = fmaxf(r1, e);
        r1 = lo; r2 = fminf(r2, hi);
    }
    float m1 = fminf(p1, r1);
    float mm = fmaxf(p1, r1);
    float m2 = fminf(fminf(p2, r2), mm);

    float v = m1;
    float T = 3.0e30f;
    #pragma unroll
    for (int k = 0; k < K; k++) {
        float m = v;
        #pragma unroll
        for (int off = 16; off > 0; off >>= 1)
            m = fminf(m, __shfl_xor_sync(0xFFFFFFFFu, m, off));
        unsigned ball = __ballot_sync(0xFFFFFFFFu, v == m);
        int src = __ffs(ball) - 1;
        if (lane == src) { v = m2; m2 = 3.0e30f; }
        T = m;
    }
    if (lane == 0) g_thr[q] = nextafterf(T, 3.4e38f);
}

// ---------------------------------------------------------------------------
// Kernel 3 (HOT): branch-free mask scan with packed FFMA2.
// ---------------------------------------------------------------------------
__global__ void __launch_bounds__(NTHR)
mask_kernel(const float* __restrict__ in) {
    __shared__ ulonglong2 shA[CHUNK / 2];
    __shared__ ulonglong2 shB[CHUNK / 2];

    int bid = blockIdx.x;                 // [0, 576)
    int c   = bid & (NCHUNKB - 1);
    int qg  = (bid >> 5) % NQG;
    int b   = bid / (NQG * NCHUNKB);

    int tid = threadIdx.x;
    int poff = b * (NPIX / 2) + c * (CHUNK / 2);
    for (int i = tid; i < CHUNK / 2; i += NTHR) {
        shA[i] = g_pairA[poff + i];
        shB[i] = g_pairB[poff + i];
    }

    int q0 = qg * QPB + tid;
    int gq = b * NPIX + q0;
    const float* base = in + (size_t)b * 3 * NPIX;
    float a0x = base[q0],            a0y = base[NPIX + q0],            a0z = base[2*NPIX + q0];
    float a1x = base[q0 + NTHR],     a1y = base[NPIX + q0 + NTHR],     a1z = base[2*NPIX + q0 + NTHR];
    float a2x = base[q0 + 2*NTHR],   a2y = base[NPIX + q0 + 2*NTHR],   a2z = base[2*NPIX + q0 + 2*NTHR];
    float a3x = base[q0 + 3*NTHR],   a3y = base[NPIX + q0 + 3*NTHR],   a3z = base[2*NPIX + q0 + 3*NTHR];
    u64 QX0 = pack2(a0x, a0x), QY0 = pack2(a0y, a0y), QZ0 = pack2(a0z, a0z);
    u64 QX1 = pack2(a1x, a1x), QY1 = pack2(a1y, a1y), QZ1 = pack2(a1z, a1z);
    u64 QX2 = pack2(a2x, a2x), QY2 = pack2(a2y, a2y), QZ2 = pack2(a2z, a2z);
    u64 QX3 = pack2(a3x, a3x), QY3 = pack2(a3y, a3y), QZ3 = pack2(a3z, a3z);

    float m0 = g_thr[gq];
    float m1 = g_thr[gq + NTHR];
    float m2 = g_thr[gq + 2 * NTHR];
    float m3 = g_thr[gq + 3 * NTHR];

    __syncthreads();

    for (int s16 = 0; s16 < CHUNK / 2; s16 += 16) {   // 16 pairs = 1 word
        unsigned M0 = 0, M1 = 0, M2 = 0, M3 = 0;
        #pragma unroll
        for (int u = 0; u < 16; u++) {
            ulonglong2 pA = shA[s16 + u];
            ulonglong2 pB = shB[s16 + u];
            u64 d0 = fma2(QX0, pA.x, fma2(QY0, pA.y, fma2(QZ0, pB.x, pB.y)));
            u64 d1 = fma2(QX1, pA.x, fma2(QY1, pA.y, fma2(QZ1, pB.x, pB.y)));
            u64 d2 = fma2(QX2, pA.x, fma2(QY2, pA.y, fma2(QZ2, pB.x, pB.y)));
            u64 d3 = fma2(QX3, pA.x, fma2(QY3, pA.y, fma2(QZ3, pB.x, pB.y)));
            float2 e0 = unpack2(d0);
            float2 e1 = unpack2(d1);
            float2 e2 = unpack2(d2);
            float2 e3 = unpack2(d3);
            if (e0.x < m0) M0 |= (1u << (2 * u));
            if (e0.y < m0) M0 |= (1u << (2 * u + 1));
            if (e1.x < m1) M1 |= (1u << (2 * u));
            if (e1.y < m1) M1 |= (1u << (2 * u + 1));
            if (e2.x < m2) M2 |= (1u << (2 * u));
            if (e2.y < m2) M2 |= (1u << (2 * u + 1));
            if (e3.x < m3) M3 |= (1u << (2 * u));
            if (e3.y < m3) M3 |= (1u << (2 * u + 1));
        }
        int w = c * WPC + (s16 >> 4);
        g_mask[w][gq]            = M0;     // coalesced across threads
        g_mask[w][gq + NTHR]     = M1;
        g_mask[w][gq + 2 * NTHR] = M2;
        g_mask[w][gq + 3 * NTHR] = M3;
    }
}

// ---------------------------------------------------------------------------
// Kernel 4: WARP-PER-QUERY select. uint4-staged masks; survivors compacted
// to a u16 index queue; balanced 32-wide processing into 4-deep ordered-uint
// lane state; REDUX.MIN 8-round merge. Fallback = exact per-lane bit-walk.
// ---------------------------------------------------------------------------
__global__ void __launch_bounds__(NTHR)
select_kernel(const float* __restrict__ in, float* __restrict__ out) {
    __shared__ unsigned smask[SWARPS][NWORDS + 1];      // +1 pad
    __shared__ unsigned short squeue[SWARPS][QCAP];
    __shared__ float red[SWARPS];
    __shared__ int islast;

    int tid  = threadIdx.x;
    int lane = tid & 31;
    int wid  = tid >> 5;
    int qbase = blockIdx.x * SWARPS;

    // vectorized mask staging: uint4 = 4 queries' copies of one word
    for (int idx = tid; idx < SWARPS * NWORDS / 4; idx += NTHR) {
        int w  = idx >> 1;
        int j4 = (idx & 1) * 4;
        uint4 v = *reinterpret_cast<const uint4*>(&g_mask[w][qbase + j4]);
        smask[j4 + 0][w] = v.x;
        smask[j4 + 1][w] = v.y;
        smask[j4 + 2][w] = v.z;
        smask[j4 + 3][w] = v.w;
    }

    int q = qbase + wid;
    int b = q / NPIX;
    int qi = q - b * NPIX;
    const float* base = in + (size_t)b * 3 * NPIX;
    float ax = base[qi], ay = base[NPIX + qi], az = base[2 * NPIX + qi];
    float q2 = fmaf(ax, ax, fmaf(ay, ay, az * az));

    __syncthreads();

    const unsigned* mw = smask[wid];
    const float4* cb = g_cand + b * NPIX;
    int w0 = lane * WPL;

    // lane survivor count + warp exclusive scan
    unsigned nl = 0;
    #pragma unroll
    for (int i = 0; i < WPL; i++) nl += __popc(mw[w0 + i]);
    unsigned pfx = nl;
    #pragma unroll
    for (int off = 1; off < 32; off <<= 1) {
        unsigned v = __shfl_up_sync(0xFFFFFFFFu, pfx, off);
        if (lane >= off) pfx += v;
    }
    unsigned total = __shfl_sync(0xFFFFFFFFu, pfx, 31);
    pfx -= nl;   // exclusive prefix

    float s = 0.0f;

    if (total <= QCAP) {
        // compact survivor candidate-indices
        int pos = pfx;
        #pragma unroll
        for (int i = 0; i < WPL; i++) {
            unsigned word = mw[w0 + i];
            while (word) {
                int bit = __ffs(word) - 1;
                word &= word - 1;
                squeue[wid][pos++] = (unsigned short)((w0 + i) * 32 + bit);
            }
        }
        __syncwarp();
        // balanced 32-wide processing; <=4 inserts per lane (total<=128)
        unsigned t[4] = {0xFFFFFFFFu, 0xFFFFFFFFu, 0xFFFFFFFFu, 0xFFFFFFFFu};
        for (unsigned bb = 0; bb < total; bb += 32) {
            unsigned ii = bb + lane;
            unsigned u = 0xFFFFFFFFu;
            if (ii < total) {
                float4 cv = cb[squeue[wid][ii]];
                float d = fmaf(ax, cv.x, fmaf(ay, cv.y, fmaf(az, cv.z, cv.w)));
                u = mapf(d);
            }
            insert4u(t, u);
        }
        // 8-round REDUX.MIN merge; k==0 pop = self distance -> skipped
        #pragma unroll
        for (int k = 0; k < K; k++) {
            unsigned m = __reduce_min_sync(0xFFFFFFFFu, t[0]);
            unsigned ball = __ballot_sync(0xFFFFFFFFu, t[0] == m);
            int src = __ffs(ball) - 1;
            if (lane == src) {
                t[0] = t[1]; t[1] = t[2]; t[2] = t[3]; t[3] = 0xFFFFFFFFu;
            }
            if (k > 0) s += sqrtf(fmaxf(unmapf(m) + q2, 0.0f));
        }
    } else {
        // exact fallback: per-lane flattened bit-walk + float shfl merge
        float t8[K];
        #pragma unroll
        for (int k = 0; k < K; k++) t8[k] = 3.0e30f;
        int wi = w0, wend = w0 + WPL;
        unsigned word = mw[wi];
        for (;;) {
            while (word == 0 && wi + 1 < wend) { wi++; word = mw[wi]; }
            if (word == 0) break;
            int bit = __ffs(word) - 1;
            word &= word - 1;
            float4 cv = cb[wi * 32 + bit];
            float d = fmaf(ax, cv.x, fmaf(ay, cv.y, fmaf(az, cv.z, cv.w)));
            insert8s(t8, d);
        }
        #pragma unroll
        for (int k = 0; k < K; k++) {
            float v = t8[0];
            float m = v;
            #pragma unroll
            for (int off = 16; off > 0; off >>= 1)
                m = fminf(m, __shfl_xor_sync(0xFFFFFFFFu, m, off));
            unsigned ball = __ballot_sync(0xFFFFFFFFu, v == m);
            int src = __ffs(ball) - 1;
            if (lane == src) {
                #pragma unroll
                for (int j = 0; j < K - 1; j++) t8[j] = t8[j + 1];
                t8[K - 1] = 3.0e30f;
            }
            if (k > 0) s += sqrtf(fmaxf(m + q2, 0.0f));
        }
    }

    if (lane == 0) red[wid] = s;
    __syncthreads();

    if (tid == 0) {
        float bs = 0.0f;
        #pragma unroll
        for (int wv = 0; wv < SWARPS; wv++) bs += red[wv];
        g_bsum[blockIdx.x] = bs;
        __threadfence();
        unsigned r = atomicAdd(&g_ticket, 1u);
        islast = (r == (unsigned)(gridDim.x - 1));
    }
    __syncthreads();

    if (islast) {
        __shared__ float red2[NTHR];
        float v = 0.0f;
        for (int i = tid; i < SBLK; i += NTHR) v += __ldcg(&g_bsum[i]);
        red2[tid] = v;
        __syncthreads();
        #pragma unroll
        for (int w = NTHR / 2; w > 0; w >>= 1) {
            if (tid < w) red2[tid] += red2[tid + w];
            __syncthreads();
        }
        if (tid == 0) {
            out[0] = -red2[0] / (float)(TOTQ * K);
            g_ticket = 0;    // reset for next graph replay
        }
    }
}

extern "C" void kernel_launch(void* const* d_in, const int* in_sizes, int n_in,
                              void* d_out, int out_size) {
    const float* in = (const float*)d_in[0];
    float* out = (float*)d_out;

    prep_kernel<<<(TOTQ + NTHR - 1) / NTHR, NTHR>>>(in);
    thresh_kernel<<<SBLK, NTHR>>>(in);
    mask_kernel<<<B * NQG * NCHUNKB, NTHR>>>(in);
    select_kernel<<<SBLK, NTHR>>>(in, out);
}